// round 14
// baseline (speedup 1.0000x reference)
#include <cuda_runtime.h>
#include <cstdint>

// SpectralConv2D, R14: two-kernel flat design, w-amplification fixed.
//  K1 (R10, proven): per input pixel scatter pre-duplicated y{v,v} into
//      tap-major planes g_y[tap][b*900+l]; build g_base[tap][f].
//  K2: block = 64 consecutive bl positions; base loaded to smem once
//      (coalesced), ONE barrier, then streaming: 18 y LDG.128 + 9 w LDS.128
//      + 36 FFMA2 per thread (4 pos x 4 filters). No input chain, no Phase B.
//   out[b,l,f] = relu( sum_tap base[f,tap] * y[tap][b,l] )

#define B_    64
#define W_    32
#define C_    8
#define F_    64
#define O2_   30
#define L_    900
#define N_    1024
#define BL_   (B_ * L_)     // 57600

// scratch (__device__ globals: allocation-free rule)
__device__ float2 g_y[9][BL_];        // pre-duplicated y, tap-major (4.15 MB)
__device__ float  g_base[9 * F_];     // [tap][f]

__constant__ int c_sel[9] = {0,1,1,2,0,1,2,2,0};
__constant__ int c_t  [9] = {0,0,1,0,1,2,1,2,2};
__constant__ int c_i  [9] = {0,0,0,1,1,1,2,2,2};
__constant__ int c_j  [9] = {0,1,2,0,1,2,0,1,2};

__device__ __forceinline__ uint64_t ffma2(uint64_t a, uint64_t b, uint64_t c) {
    uint64_t d;
    asm("fma.rn.f32x2 %0, %1, %2, %3;" : "=l"(d) : "l"(a), "l"(b), "l"(c));
    return d;
}
__device__ __forceinline__ uint64_t fmul2(uint64_t a, uint64_t b) {
    uint64_t d;
    asm("mul.rn.f32x2 %0, %1, %2;" : "=l"(d) : "l"(a), "l"(b));
    return d;
}
__device__ __forceinline__ float2 u64_as_f2(uint64_t v) {
    union { uint64_t u; float2 f; } cv; cv.u = v; return cv.f;
}

// ---------------- K1: pixel scatter + base assembly (R10, proven) ----------------
__global__ __launch_bounds__(256)
void prep_kernel(const float* __restrict__ inputs,      // (B,32,32,8)
                 const float* __restrict__ omega_diag,
                 const float* __restrict__ omega_triu,
                 const float* __restrict__ omega_tril,
                 const float* __restrict__ lambda_in,
                 const float* __restrict__ lambda_out,
                 const float* __restrict__ use_encode,  // (N)
                 const float* __restrict__ use_decode)  // (L)
{
    int pid = blockIdx.x * 256 + threadIdx.x;  // 0..65535
    int b = pid >> 10;
    int n = pid & 1023;
    int r = n >> 5;
    int c = n & 31;

    const float4* p = (const float4*)(inputs + (size_t)pid * C_);
    float4 v0 = p[0];
    float4 v1 = p[1];
    float m  = (v0.x + v0.y + v0.z + v0.w + v1.x + v1.y + v1.z + v1.w) * 0.125f;
    float eu = m * __ldg(&use_encode[n]);

    int blb = b * L_;
    #pragma unroll
    for (int tap = 0; tap < 9; tap++) {
        int rr = r - tap / 3;
        int cc = c - tap % 3;
        if (rr >= 0 && rr < O2_ && cc >= 0 && cc < O2_) {
            int l = rr * O2_ + cc;
            float v = eu - __ldg(&use_decode[l]) * m;
            g_y[tap][blb + l] = make_float2(v, v);
        }
    }

    // base assembly (block 0 only): g_base[tap][f]
    if (blockIdx.x == 0) {
        const float* srcs[3] = { omega_diag, omega_triu, omega_tril };
        for (int idx = threadIdx.x; idx < 9 * F_; idx += 256) {
            int pp = idx >> 6;
            int f  = idx & 63;
            float w   = __ldg(&srcs[c_sel[pp]][f * 3 + c_t[pp]]);
            float lam = __ldg(&lambda_in[c_i[pp]]) - __ldg(&lambda_out[c_j[pp]]);
            g_base[idx] = w * lam;
        }
    }
}

// ---------------- K2: streaming compute ----------------
// block = 64 consecutive bl; thread = (g = pos-quad 0..15, f4 = filter-quad 0..15)
__global__ __launch_bounds__(256)
void conv_kernel(float* __restrict__ out)   // (B*L, F)
{
    __shared__ __align__(16) float base_s[9 * F_];

    const int tid = threadIdx.x;
    const int f4  = tid & 15;
    const int g   = tid >> 4;               // 0..15
    const int bl0 = blockIdx.x * 64;        // 900 blocks * 64 = 57600 exact

    // coalesced base load: 576 floats = 144 float4
    if (tid < 144)
        ((float4*)base_s)[tid] = __ldg(&((const float4*)g_base)[tid]);
    __syncthreads();

    const int blq = bl0 + g * 4;            // 4 consecutive positions

    uint64_t acc[4][2];
    #pragma unroll
    for (int tap = 0; tap < 9; tap++) {
        ulonglong2 wv = *(const ulonglong2*)(base_s + tap * F_ + f4 * 4);
        const ulonglong2* yp = (const ulonglong2*)&g_y[tap][blq];  // dup pairs
        ulonglong2 y01 = __ldg((const ulonglong2*)yp);
        ulonglong2 y23 = __ldg(((const ulonglong2*)yp) + 1);
        if (tap == 0) {
            acc[0][0] = fmul2(y01.x, wv.x); acc[0][1] = fmul2(y01.x, wv.y);
            acc[1][0] = fmul2(y01.y, wv.x); acc[1][1] = fmul2(y01.y, wv.y);
            acc[2][0] = fmul2(y23.x, wv.x); acc[2][1] = fmul2(y23.x, wv.y);
            acc[3][0] = fmul2(y23.y, wv.x); acc[3][1] = fmul2(y23.y, wv.y);
        } else {
            acc[0][0] = ffma2(y01.x, wv.x, acc[0][0]); acc[0][1] = ffma2(y01.x, wv.y, acc[0][1]);
            acc[1][0] = ffma2(y01.y, wv.x, acc[1][0]); acc[1][1] = ffma2(y01.y, wv.y, acc[1][1]);
            acc[2][0] = ffma2(y23.x, wv.x, acc[2][0]); acc[2][1] = ffma2(y23.x, wv.y, acc[2][1]);
            acc[3][0] = ffma2(y23.y, wv.x, acc[3][0]); acc[3][1] = ffma2(y23.y, wv.y, acc[3][1]);
        }
    }

    float* obase = out + (size_t)blq * F_ + f4 * 4;
    #pragma unroll
    for (int k = 0; k < 4; k++) {
        float2 a0 = u64_as_f2(acc[k][0]);
        float2 a1 = u64_as_f2(acc[k][1]);
        float4 o;
        o.x = fmaxf(a0.x, 0.f);
        o.y = fmaxf(a0.y, 0.f);
        o.z = fmaxf(a1.x, 0.f);
        o.w = fmaxf(a1.y, 0.f);
        *(float4*)(obase + k * F_) = o;
    }
}

extern "C" void kernel_launch(void* const* d_in, const int* in_sizes, int n_in,
                              void* d_out, int out_size) {
    (void)in_sizes; (void)n_in; (void)out_size;
    const float* inputs      = (const float*)d_in[0];
    const float* omega_diag  = (const float*)d_in[1];
    const float* omega_triu  = (const float*)d_in[2];
    const float* omega_tril  = (const float*)d_in[3];
    const float* lambda_in   = (const float*)d_in[4];
    const float* lambda_out  = (const float*)d_in[5];
    const float* use_encode  = (const float*)d_in[6];
    const float* use_decode  = (const float*)d_in[7];
    float* out = (float*)d_out;

    prep_kernel<<<256, 256>>>(inputs, omega_diag, omega_triu, omega_tril,
                              lambda_in, lambda_out, use_encode, use_decode);
    conv_kernel<<<900, 256>>>(out);
}